// round 4
// baseline (speedup 1.0000x reference)
#include <cuda_runtime.h>
#include <math.h>
#include <stdint.h>

// ---------------- problem constants ----------------
#define BB    256
#define CDDN  5
#define HISN  50
#define TT    20
#define DD    300
#define HH    16
#define VDIM  16
#define RPR   256
#define QDQ   200
#define NITEMS (BB*(CDDN+HISN))
#define SCALE 0.05773502691896258f   // 1/sqrt(300), both levels

// ---------------- device scratch ----------------
__device__ float g_cdd[BB*CDDN*RPR];
__device__ float g_his[BB*HISN*RPR];
__device__ float g_nval[BB*HISN*RPR];
__device__ float g_user[BB*RPR];

// ---------------- packed f32x2 helpers ----------------
__device__ __forceinline__ uint64_t pk2(float a, float b){
    uint64_t r; asm("mov.b64 %0,{%1,%2};" : "=l"(r) : "f"(a), "f"(b)); return r;
}
__device__ __forceinline__ void fma2(uint64_t& d, uint64_t a, uint64_t b){
    asm("fma.rn.f32x2 %0,%1,%2,%0;" : "+l"(d) : "l"(a), "l"(b));
}
__device__ __forceinline__ float2 up2(uint64_t v){
    float2 f; asm("mov.b64 {%0,%1},%2;" : "=f"(f.x), "=f"(f.y) : "l"(v)); return f;
}

extern __shared__ float sm[];

// ================= word-level encoder: one CTA (640 thr) per news item =================
// smem: xT[300][24] | qT[4][300][21] | V[20][256] | val[20][256] | attn[4][20][21] | wl[20]
#define W_XP 24
#define W_QP 21
#define W_QT_OFF  (300*W_XP)                 // 7200
#define W_V_OFF   (W_QT_OFF + 4*300*W_QP)    // 32400
#define W_VAL_OFF (W_V_OFF  + TT*RPR)        // 37520
#define W_ATT_OFF (W_VAL_OFF + TT*RPR)       // 42640
#define W_WL_OFF  (W_ATT_OFF + 4*TT*21)      // 44320
#define W_SMEM_FLOATS (W_WL_OFF + TT)        // 44340  (177.4 KB)

__global__ __launch_bounds__(640, 1)
void word_kernel(const int* __restrict__ cand, const int* __restrict__ clicked,
                 const float* __restrict__ emb,
                 const float* __restrict__ Wq, const float* __restrict__ Wv,
                 const float* __restrict__ Wk, const float* __restrict__ bk,
                 const float* __restrict__ qv)
{
    float* xT   = sm;
    float* qT   = sm + W_QT_OFF;
    float* V    = sm + W_V_OFF;
    float* val  = sm + W_VAL_OFF;
    float* attn = sm + W_ATT_OFF;
    float* wl   = sm + W_WL_OFF;
    __shared__ int tok[TT];

    const int tid  = threadIdx.x;
    const int item = blockIdx.x;

    const int* tp = (item < BB*CDDN) ? (cand + item*TT)
                                     : (clicked + (item - BB*CDDN)*TT);
    if (tid < TT) tok[tid] = tp[tid];
    __syncthreads();

    // gather x transposed
    for (int p = tid; p < TT*DD; p += 640) {
        int s = p / DD, f = p - s*DD;
        xT[f*W_XP + s] = emb[tok[s]*DD + f];
    }
    __syncthreads();

    // ---- V = x @ Wv_all : quad columns, f32x2 ----
    for (int p = tid; p < TT*64; p += 640) {
        int s = p >> 6, cq = p & 63, c = cq*4;
        int h = c >> 4, v = c & 15;
        const float* w = Wv + h*(DD*VDIM) + v;
        uint64_t a0 = 0, a1 = 0;
        #pragma unroll 2
        for (int f = 0; f < DD; f++) {
            float xv = xT[f*W_XP + s];
            uint64_t px = pk2(xv, xv);
            ulonglong2 wv = *(const ulonglong2*)(w + f*VDIM);
            fma2(a0, px, wv.x); fma2(a1, px, wv.y);
        }
        float2 r0 = up2(a0), r1 = up2(a1);
        *(float4*)(V + s*RPR + c) = make_float4(r0.x, r0.y, r1.x, r1.y);
    }
    __syncthreads();

    const int grp = tid / 160;        // 4 head groups of 160 (150 active)
    const int t   = tid % 160;

    for (int g = 0; g < 4; g++) {
        // ---- Q for 4 heads: thread owns 2 columns, s-pairs packed in f32x2 ----
        if (t < 150) {
            const int h = g*4 + grp;
            const float* wq = Wq + (size_t)h*(DD*DD) + 2*t;
            uint64_t acc[20];
            #pragma unroll
            for (int k = 0; k < 20; k++) acc[k] = 0ull;
            #pragma unroll 1
            for (int f = 0; f < DD; f++) {
                float2 w = *(const float2*)(wq + f*DD);
                uint64_t p0 = pk2(w.x, w.x), p1 = pk2(w.y, w.y);
                const ulonglong2* xr = (const ulonglong2*)(xT + f*W_XP);
                ulonglong2 x0 = xr[0], x1 = xr[1], x2 = xr[2], x3 = xr[3], x4 = xr[4];
                fma2(acc[0], x0.x, p0);  fma2(acc[10], x0.x, p1);
                fma2(acc[1], x0.y, p0);  fma2(acc[11], x0.y, p1);
                fma2(acc[2], x1.x, p0);  fma2(acc[12], x1.x, p1);
                fma2(acc[3], x1.y, p0);  fma2(acc[13], x1.y, p1);
                fma2(acc[4], x2.x, p0);  fma2(acc[14], x2.x, p1);
                fma2(acc[5], x2.y, p0);  fma2(acc[15], x2.y, p1);
                fma2(acc[6], x3.x, p0);  fma2(acc[16], x3.x, p1);
                fma2(acc[7], x3.y, p0);  fma2(acc[17], x3.y, p1);
                fma2(acc[8], x4.x, p0);  fma2(acc[18], x4.x, p1);
                fma2(acc[9], x4.y, p0);  fma2(acc[19], x4.y, p1);
            }
            float* q0 = qT + grp*(300*W_QP) + (2*t)*W_QP;
            float* q1 = q0 + W_QP;
            #pragma unroll
            for (int k = 0; k < 10; k++) {
                float2 a = up2(acc[k]);    q0[2*k] = a.x; q0[2*k+1] = a.y;
                float2 b = up2(acc[10+k]); q1[2*k] = b.x; q1[2*k+1] = b.y;
            }
        }
        __syncthreads();

        // ---- logits: u-quad per thread (4 heads x 100) ----
        if (tid < 400) {
            int hl = tid/100, r = tid%100, s = r%20, uq = r/20;
            const float* qh = qT + hl*(300*W_QP);
            uint64_t a0 = 0, a1 = 0;
            #pragma unroll 2
            for (int e = 0; e < DD; e++) {
                float q = qh[e*W_QP + s];
                uint64_t pq = pk2(q, q);
                ulonglong2 xv = *(const ulonglong2*)(xT + e*W_XP + uq*4);
                fma2(a0, pq, xv.x); fma2(a1, pq, xv.y);
            }
            float2 r0 = up2(a0), r1 = up2(a1);
            float* ar = attn + (hl*TT + s)*21 + uq*4;
            ar[0]=r0.x*SCALE; ar[1]=r0.y*SCALE; ar[2]=r1.x*SCALE; ar[3]=r1.y*SCALE;
        }
        __syncthreads();

        // ---- softmax rows (4 heads x 20) ----
        if (tid < 80) {
            float* row = attn + tid*21;
            float m = row[0];
            #pragma unroll
            for (int u = 1; u < TT; u++) m = fmaxf(m, row[u]);
            float sum = 0.f;
            #pragma unroll
            for (int u = 0; u < TT; u++) { float e = __expf(row[u]-m); row[u]=e; sum+=e; }
            float inv = 1.f/sum;
            #pragma unroll
            for (int u = 0; u < TT; u++) row[u] *= inv;
        }
        __syncthreads();

        // ---- val = attn @ V (4 heads) ----
        for (int p = tid; p < 4*TT*VDIM; p += 640) {
            int hl = p/320, rm = p%320, s = rm>>4, v = rm&15;
            int h = g*4 + hl;
            const float* ar = attn + (hl*TT + s)*21;
            const float* vc = V + h*VDIM + v;
            float a = 0.f;
            #pragma unroll
            for (int u = 0; u < TT; u++) a += ar[u]*vc[u*RPR];
            val[s*RPR + h*VDIM + v] = a;
        }
        __syncthreads();
    }

    // ---- additive pooling: k-quads, f32x2 ----
    if (tid < TT) wl[tid] = 0.f;
    __syncthreads();
    for (int p = tid; p < TT*50; p += 640) {
        int s = p/50, kq = p%50, k = kq*4;
        float4 b4 = *(const float4*)(bk + k);
        uint64_t a0 = pk2(b4.x, b4.y), a1 = pk2(b4.z, b4.w);
        const float* vr  = val + s*RPR;
        const float* wkp = Wk + k;
        #pragma unroll 2
        for (int r = 0; r < RPR; r++) {
            uint64_t pv = pk2(vr[r], vr[r]);
            ulonglong2 wv = *(const ulonglong2*)(wkp + r*QDQ);
            fma2(a0, pv, wv.x); fma2(a1, pv, wv.y);
        }
        float2 r0 = up2(a0), r1 = up2(a1);
        float4 q4 = *(const float4*)(qv + k);
        float ts = tanhf(r0.x)*q4.x + tanhf(r0.y)*q4.y + tanhf(r1.x)*q4.z + tanhf(r1.y)*q4.w;
        atomicAdd(&wl[s], ts);
    }
    __syncthreads();
    if (tid == 0) {
        float m = -1e30f;
        for (int s = 0; s < TT; s++) { wl[s] *= SCALE; m = fmaxf(m, wl[s]); }
        float sum = 0.f;
        for (int s = 0; s < TT; s++) { float e = __expf(wl[s]-m); wl[s]=e; sum+=e; }
        float inv = 1.f/sum;
        for (int s = 0; s < TT; s++) wl[s] *= inv;
    }
    __syncthreads();
    if (tid < RPR) {
        float a = 0.f;
        #pragma unroll
        for (int s = 0; s < TT; s++) a += wl[s] * val[s*RPR + tid];
        float* outp = (item < BB*CDDN) ? (g_cdd + item*RPR)
                                       : (g_his + (item - BB*CDDN)*RPR);
        outp[tid] = a;
    }
}

// ================= news level: (b,h)-parallel attention =================
// smem: xT[256][52] | qT[256][51] | attn[50][51] | Vh[50][16]
#define NA_XP 52
#define NA_QP 51
#define NA_QT_OFF (256*NA_XP)                 // 13312
#define NA_AT_OFF (NA_QT_OFF + 256*NA_QP)     // 26368
#define NA_V_OFF  (NA_AT_OFF + 50*51 + 2)     // 28920  (16B-aligned: fix for R2 fault)
#define NA_SMEM_FLOATS (NA_V_OFF + 50*16)     // 29720 (118.9 KB)

__global__ __launch_bounds__(256, 1)
void news_attn_kernel(const float* __restrict__ Wq, const float* __restrict__ Wv)
{
    float* xT   = sm;
    float* qT   = sm + NA_QT_OFF;
    float* attn = sm + NA_AT_OFF;
    float* Vh   = sm + NA_V_OFF;

    const int tid = threadIdx.x;
    const int h   = blockIdx.x;
    const int b   = blockIdx.y;
    const float* x = g_his + b*HISN*RPR;     // [50][256]

    for (int p = tid; p < HISN*RPR; p += 256) {
        int f = p & 255, s = p >> 8;
        xT[f*NA_XP + s] = x[p];
    }
    for (int p = tid; p < 512; p += 256)       // zero pad cols 50,51
        xT[(p>>1)*NA_XP + 50 + (p&1)] = 0.f;
    __syncthreads();

    // Vh = x @ Wv_h : 50x4 quad jobs
    if (tid < 200) {
        int s = tid >> 2, v = (tid & 3)*4;
        const float* w = Wv + h*(RPR*VDIM) + v;
        uint64_t a0 = 0, a1 = 0;
        #pragma unroll 2
        for (int f = 0; f < RPR; f++) {
            float xv = xT[f*NA_XP + s];
            uint64_t px = pk2(xv, xv);
            ulonglong2 wv = *(const ulonglong2*)(w + f*VDIM);
            fma2(a0, px, wv.x); fma2(a1, px, wv.y);
        }
        float2 r0 = up2(a0), r1 = up2(a1);
        *(float4*)(Vh + s*16 + v) = make_float4(r0.x, r0.y, r1.x, r1.y);
    }

    // Q_h: thread = column tid, 25 s-pairs
    {
        uint64_t acc[25];
        #pragma unroll
        for (int k = 0; k < 25; k++) acc[k] = 0ull;
        const float* wq = Wq + (size_t)h*(RPR*RPR) + tid;
        #pragma unroll 1
        for (int f = 0; f < RPR; f++) {
            float w = wq[f*RPR];
            uint64_t pw = pk2(w, w);
            const ulonglong2* xr = (const ulonglong2*)(xT + f*NA_XP);
            #pragma unroll
            for (int k = 0; k < 12; k++) {
                ulonglong2 xv = xr[k];
                fma2(acc[2*k],   xv.x, pw);
                fma2(acc[2*k+1], xv.y, pw);
            }
            uint64_t xt = *(const uint64_t*)(xT + f*NA_XP + 48);
            fma2(acc[24], xt, pw);
        }
        float* q0 = qT + tid*NA_QP;
        #pragma unroll
        for (int k = 0; k < 25; k++) {
            float2 a = up2(acc[k]); q0[2*k] = a.x; q0[2*k+1] = a.y;
        }
    }
    __syncthreads();

    // logits: u-quads, 50x13 jobs
    for (int p = tid; p < 650; p += 256) {
        int s = p % 50, uq = p / 50, u = uq*4;
        uint64_t a0 = 0, a1 = 0;
        #pragma unroll 2
        for (int e = 0; e < RPR; e++) {
            float q = qT[e*NA_QP + s];
            uint64_t pq = pk2(q, q);
            ulonglong2 xv = *(const ulonglong2*)(xT + e*NA_XP + u);
            fma2(a0, pq, xv.x); fma2(a1, pq, xv.y);
        }
        float2 r0 = up2(a0), r1 = up2(a1);
        float* ar = attn + s*51;
        ar[u] = r0.x*SCALE;
        if (u+1 < 50) ar[u+1] = r0.y*SCALE;
        if (u+2 < 50) { ar[u+2] = r1.x*SCALE; ar[u+3] = r1.y*SCALE; }
    }
    __syncthreads();

    if (tid < 50) {
        float* row = attn + tid*51;
        float m = row[0];
        for (int u = 1; u < 50; u++) m = fmaxf(m, row[u]);
        float sum = 0.f;
        for (int u = 0; u < 50; u++) { float e = __expf(row[u]-m); row[u]=e; sum+=e; }
        float inv = 1.f/sum;
        for (int u = 0; u < 50; u++) row[u] *= inv;
    }
    __syncthreads();

    for (int p = tid; p < 800; p += 256) {
        int s = p >> 4, v = p & 15;
        const float* ar = attn + s*51;
        float a = 0.f;
        #pragma unroll 10
        for (int u = 0; u < 50; u++) a += ar[u]*Vh[u*16 + v];
        g_nval[(b*HISN + s)*RPR + h*VDIM + v] = a;
    }
}

// ================= news pooling =================
#define NP_SMEM_FLOATS (HISN*RPR + HISN)      // 12850 (51.4 KB)

__global__ __launch_bounds__(256, 2)
void news_pool_kernel(const float* __restrict__ Wk, const float* __restrict__ bk,
                      const float* __restrict__ qv)
{
    float* val = sm;
    float* wl  = sm + HISN*RPR;
    const int tid = threadIdx.x;
    const int b   = blockIdx.x;

    for (int p = tid; p < HISN*RPR; p += 256) val[p] = g_nval[b*HISN*RPR + p];
    if (tid < HISN) wl[tid] = 0.f;
    __syncthreads();

    for (int p = tid; p < HISN*50; p += 256) {
        int s = p/50, kq = p%50, k = kq*4;
        float4 b4 = *(const float4*)(bk + k);
        uint64_t a0 = pk2(b4.x, b4.y), a1 = pk2(b4.z, b4.w);
        const float* vr  = val + s*RPR;
        const float* wkp = Wk + k;
        #pragma unroll 2
        for (int r = 0; r < RPR; r++) {
            uint64_t pv = pk2(vr[r], vr[r]);
            ulonglong2 wv = *(const ulonglong2*)(wkp + r*QDQ);
            fma2(a0, pv, wv.x); fma2(a1, pv, wv.y);
        }
        float2 r0 = up2(a0), r1 = up2(a1);
        float4 q4 = *(const float4*)(qv + k);
        float ts = tanhf(r0.x)*q4.x + tanhf(r0.y)*q4.y + tanhf(r1.x)*q4.z + tanhf(r1.y)*q4.w;
        atomicAdd(&wl[s], ts);
    }
    __syncthreads();
    if (tid == 0) {
        float m = -1e30f;
        for (int s = 0; s < HISN; s++) { wl[s] *= SCALE; m = fmaxf(m, wl[s]); }
        float sum = 0.f;
        for (int s = 0; s < HISN; s++) { float e = __expf(wl[s]-m); wl[s]=e; sum+=e; }
        float inv = 1.f/sum;
        for (int s = 0; s < HISN; s++) wl[s] *= inv;
    }
    __syncthreads();
    if (tid < RPR) {
        float a = 0.f;
        #pragma unroll 10
        for (int s = 0; s < HISN; s++) a += wl[s] * val[s*RPR + tid];
        g_user[b*RPR + tid] = a;
    }
}

// ================= scores + log_softmax =================
__global__ void score_kernel(float* __restrict__ out)
{
    __shared__ float sc[CDDN];
    const int b = blockIdx.x;
    const int w = threadIdx.x >> 5, lane = threadIdx.x & 31;
    if (w < CDDN) {
        const float* c = g_cdd + (b*CDDN + w)*RPR;
        const float* u = g_user + b*RPR;
        float a = 0.f;
        #pragma unroll
        for (int k = lane; k < RPR; k += 32) a += c[k]*u[k];
        #pragma unroll
        for (int off = 16; off; off >>= 1) a += __shfl_down_sync(0xffffffffu, a, off);
        if (lane == 0) sc[w] = a;
    }
    __syncthreads();
    if (threadIdx.x == 0) {
        float m = sc[0];
        for (int c = 1; c < CDDN; c++) m = fmaxf(m, sc[c]);
        float sum = 0.f;
        for (int c = 0; c < CDDN; c++) sum += __expf(sc[c]-m);
        float lse = logf(sum) + m;
        for (int c = 0; c < CDDN; c++) out[b*CDDN + c] = sc[c] - lse;
    }
}

// ================= launch =================
extern "C" void kernel_launch(void* const* d_in, const int* in_sizes, int n_in,
                              void* d_out, int out_size)
{
    (void)in_sizes; (void)n_in; (void)out_size;
    const int*   cand    = (const int*)d_in[0];
    const int*   clicked = (const int*)d_in[1];
    const float* emb     = (const float*)d_in[2];
    const float* Wq_w    = (const float*)d_in[3];
    const float* Wv_w    = (const float*)d_in[4];
    const float* Wk_w    = (const float*)d_in[5];
    const float* bk_w    = (const float*)d_in[6];
    const float* q_w     = (const float*)d_in[7];
    const float* Wq_n    = (const float*)d_in[8];
    const float* Wv_n    = (const float*)d_in[9];
    const float* Wk_n    = (const float*)d_in[10];
    const float* bk_n    = (const float*)d_in[11];
    const float* q_n     = (const float*)d_in[12];
    float* out = (float*)d_out;

    const size_t smw  = W_SMEM_FLOATS  * sizeof(float);
    const size_t smna = NA_SMEM_FLOATS * sizeof(float);
    const size_t smnp = NP_SMEM_FLOATS * sizeof(float);
    cudaFuncSetAttribute(word_kernel,      cudaFuncAttributeMaxDynamicSharedMemorySize, (int)smw);
    cudaFuncSetAttribute(news_attn_kernel, cudaFuncAttributeMaxDynamicSharedMemorySize, (int)smna);
    cudaFuncSetAttribute(news_pool_kernel, cudaFuncAttributeMaxDynamicSharedMemorySize, (int)smnp);

    word_kernel<<<NITEMS, 640, smw>>>(cand, clicked, emb, Wq_w, Wv_w, Wk_w, bk_w, q_w);
    news_attn_kernel<<<dim3(HH, BB), 256, smna>>>(Wq_n, Wv_n);
    news_pool_kernel<<<BB, 256, smnp>>>(Wk_n, bk_n, q_n);
    score_kernel<<<BB, 192>>>(out);
}

// round 5
// speedup vs baseline: 1.3775x; 1.3775x over previous
#include <cuda_runtime.h>
#include <math.h>
#include <stdint.h>

// ---------------- problem constants ----------------
#define BB    256
#define CDDN  5
#define HISN  50
#define TT    20
#define DD    300
#define HH    16
#define VDIM  16
#define RPR   256
#define QDQ   200
#define NITEMS (BB*(CDDN+HISN))
#define SCALE 0.05773502691896258f   // 1/sqrt(300), both levels

// ---------------- device scratch ----------------
__device__ float g_cdd[BB*CDDN*RPR];
__device__ float g_his[BB*HISN*RPR];
__device__ float g_nval[BB*HISN*RPR];
__device__ float g_user[BB*RPR];

// ---------------- packed f32x2 helpers ----------------
__device__ __forceinline__ uint64_t pk2(float a, float b){
    uint64_t r; asm("mov.b64 %0,{%1,%2};" : "=l"(r) : "f"(a), "f"(b)); return r;
}
__device__ __forceinline__ void fma2(uint64_t& d, uint64_t a, uint64_t b){
    asm("fma.rn.f32x2 %0,%1,%2,%0;" : "+l"(d) : "l"(a), "l"(b));
}
__device__ __forceinline__ float2 up2(uint64_t v){
    float2 f; asm("mov.b64 {%0,%1},%2;" : "=f"(f.x), "=f"(f.y) : "l"(v)); return f;
}

extern __shared__ float sm[];

// ================= word-level encoder: one CTA (640 thr) per news item =================
// smem: xT[300][24] | qT[4][300][21] | V[20][256] | val[20][256] | attn[4][20][21] | wl[20]
#define W_XP 24
#define W_QP 21
#define W_QT_OFF  (300*W_XP)                 // 7200
#define W_V_OFF   (W_QT_OFF + 4*300*W_QP)    // 32400
#define W_VAL_OFF (W_V_OFF  + TT*RPR)        // 37520
#define W_ATT_OFF (W_VAL_OFF + TT*RPR)       // 42640
#define W_WL_OFF  (W_ATT_OFF + 4*TT*21)      // 44320
#define W_SMEM_FLOATS (W_WL_OFF + TT)        // 44340  (177.4 KB)

__global__ __launch_bounds__(640, 1)
void word_kernel(const int* __restrict__ cand, const int* __restrict__ clicked,
                 const float* __restrict__ emb,
                 const float* __restrict__ Wq, const float* __restrict__ Wv,
                 const float* __restrict__ Wk, const float* __restrict__ bk,
                 const float* __restrict__ qv)
{
    float* xT   = sm;
    float* qT   = sm + W_QT_OFF;
    float* V    = sm + W_V_OFF;
    float* val  = sm + W_VAL_OFF;
    float* attn = sm + W_ATT_OFF;
    float* wl   = sm + W_WL_OFF;
    __shared__ int tok[TT];

    const int tid  = threadIdx.x;
    const int item = blockIdx.x;

    const int* tp = (item < BB*CDDN) ? (cand + item*TT)
                                     : (clicked + (item - BB*CDDN)*TT);
    if (tid < TT) tok[tid] = tp[tid];
    __syncthreads();

    // gather x transposed
    for (int p = tid; p < TT*DD; p += 640) {
        int s = p / DD, f = p - s*DD;
        xT[f*W_XP + s] = emb[tok[s]*DD + f];
    }
    __syncthreads();

    // ---- V = x @ Wv_all : quad columns, f32x2, MLP-4 on Wv loads ----
    for (int p = tid; p < TT*64; p += 640) {
        int s = p >> 6, cq = p & 63, c = cq*4;
        int h = c >> 4, v = c & 15;
        const float* w = Wv + h*(DD*VDIM) + v;
        uint64_t a0 = 0, a1 = 0;
        #pragma unroll 4
        for (int f = 0; f < DD; f++) {
            float xv = xT[f*W_XP + s];
            uint64_t px = pk2(xv, xv);
            ulonglong2 wv = *(const ulonglong2*)(w + f*VDIM);
            fma2(a0, px, wv.x); fma2(a1, px, wv.y);
        }
        float2 r0 = up2(a0), r1 = up2(a1);
        *(float4*)(V + s*RPR + c) = make_float4(r0.x, r0.y, r1.x, r1.y);
    }
    __syncthreads();

    const int grp = tid / 160;        // 4 head groups of 160 (150 active)
    const int t   = tid % 160;

    for (int g = 0; g < 4; g++) {
        // ---- Q for 4 heads: thread owns 2 columns; manual unroll-2 over f
        //      with both Wq loads hoisted (MLP 2 on the L2-latency path) ----
        if (t < 150) {
            const int h = g*4 + grp;
            const float* wq = Wq + (size_t)h*(DD*DD) + 2*t;
            uint64_t acc[20];
            #pragma unroll
            for (int k = 0; k < 20; k++) acc[k] = 0ull;
            #pragma unroll 1
            for (int f = 0; f < DD; f += 2) {
                float2 wA = *(const float2*)(wq + f*DD);
                float2 wB = *(const float2*)(wq + (f+1)*DD);
                {
                    uint64_t p0 = pk2(wA.x, wA.x), p1 = pk2(wA.y, wA.y);
                    const ulonglong2* xr = (const ulonglong2*)(xT + f*W_XP);
                    ulonglong2 x0 = xr[0], x1 = xr[1], x2 = xr[2], x3 = xr[3], x4 = xr[4];
                    fma2(acc[0], x0.x, p0);  fma2(acc[10], x0.x, p1);
                    fma2(acc[1], x0.y, p0);  fma2(acc[11], x0.y, p1);
                    fma2(acc[2], x1.x, p0);  fma2(acc[12], x1.x, p1);
                    fma2(acc[3], x1.y, p0);  fma2(acc[13], x1.y, p1);
                    fma2(acc[4], x2.x, p0);  fma2(acc[14], x2.x, p1);
                    fma2(acc[5], x2.y, p0);  fma2(acc[15], x2.y, p1);
                    fma2(acc[6], x3.x, p0);  fma2(acc[16], x3.x, p1);
                    fma2(acc[7], x3.y, p0);  fma2(acc[17], x3.y, p1);
                    fma2(acc[8], x4.x, p0);  fma2(acc[18], x4.x, p1);
                    fma2(acc[9], x4.y, p0);  fma2(acc[19], x4.y, p1);
                }
                {
                    uint64_t p0 = pk2(wB.x, wB.x), p1 = pk2(wB.y, wB.y);
                    const ulonglong2* xr = (const ulonglong2*)(xT + (f+1)*W_XP);
                    ulonglong2 x0 = xr[0], x1 = xr[1], x2 = xr[2], x3 = xr[3], x4 = xr[4];
                    fma2(acc[0], x0.x, p0);  fma2(acc[10], x0.x, p1);
                    fma2(acc[1], x0.y, p0);  fma2(acc[11], x0.y, p1);
                    fma2(acc[2], x1.x, p0);  fma2(acc[12], x1.x, p1);
                    fma2(acc[3], x1.y, p0);  fma2(acc[13], x1.y, p1);
                    fma2(acc[4], x2.x, p0);  fma2(acc[14], x2.x, p1);
                    fma2(acc[5], x2.y, p0);  fma2(acc[15], x2.y, p1);
                    fma2(acc[6], x3.x, p0);  fma2(acc[16], x3.x, p1);
                    fma2(acc[7], x3.y, p0);  fma2(acc[17], x3.y, p1);
                    fma2(acc[8], x4.x, p0);  fma2(acc[18], x4.x, p1);
                    fma2(acc[9], x4.y, p0);  fma2(acc[19], x4.y, p1);
                }
            }
            float* q0 = qT + grp*(300*W_QP) + (2*t)*W_QP;
            float* q1 = q0 + W_QP;
            #pragma unroll
            for (int k = 0; k < 10; k++) {
                float2 a = up2(acc[k]);    q0[2*k] = a.x; q0[2*k+1] = a.y;
                float2 b = up2(acc[10+k]); q1[2*k] = b.x; q1[2*k+1] = b.y;
            }
        }
        __syncthreads();

        // ---- logits: u-quad per thread (4 heads x 100), unroll 4 ----
        if (tid < 400) {
            int hl = tid/100, r = tid%100, s = r%20, uq = r/20;
            const float* qh = qT + hl*(300*W_QP);
            uint64_t a0 = 0, a1 = 0;
            #pragma unroll 4
            for (int e = 0; e < DD; e++) {
                float q = qh[e*W_QP + s];
                uint64_t pq = pk2(q, q);
                ulonglong2 xv = *(const ulonglong2*)(xT + e*W_XP + uq*4);
                fma2(a0, pq, xv.x); fma2(a1, pq, xv.y);
            }
            float2 r0 = up2(a0), r1 = up2(a1);
            float* ar = attn + (hl*TT + s)*21 + uq*4;
            ar[0]=r0.x*SCALE; ar[1]=r0.y*SCALE; ar[2]=r1.x*SCALE; ar[3]=r1.y*SCALE;
        }
        __syncthreads();

        // ---- softmax rows (4 heads x 20) ----
        if (tid < 80) {
            float* row = attn + tid*21;
            float m = row[0];
            #pragma unroll
            for (int u = 1; u < TT; u++) m = fmaxf(m, row[u]);
            float sum = 0.f;
            #pragma unroll
            for (int u = 0; u < TT; u++) { float e = __expf(row[u]-m); row[u]=e; sum+=e; }
            float inv = 1.f/sum;
            #pragma unroll
            for (int u = 0; u < TT; u++) row[u] *= inv;
        }
        __syncthreads();

        // ---- val = attn @ V (4 heads) ----
        for (int p = tid; p < 4*TT*VDIM; p += 640) {
            int hl = p/320, rm = p%320, s = rm>>4, v = rm&15;
            int h = g*4 + hl;
            const float* ar = attn + (hl*TT + s)*21;
            const float* vc = V + h*VDIM + v;
            float a = 0.f;
            #pragma unroll
            for (int u = 0; u < TT; u++) a += ar[u]*vc[u*RPR];
            val[s*RPR + h*VDIM + v] = a;
        }
        __syncthreads();
    }

    // ---- additive pooling: k-quads, f32x2, MLP-8 on Wk loads ----
    if (tid < TT) wl[tid] = 0.f;
    __syncthreads();
    for (int p = tid; p < TT*50; p += 640) {
        int s = p/50, kq = p%50, k = kq*4;
        float4 b4 = *(const float4*)(bk + k);
        uint64_t a0 = pk2(b4.x, b4.y), a1 = pk2(b4.z, b4.w);
        const float* vr  = val + s*RPR;
        const float* wkp = Wk + k;
        #pragma unroll 8
        for (int r = 0; r < RPR; r++) {
            uint64_t pv = pk2(vr[r], vr[r]);
            ulonglong2 wv = *(const ulonglong2*)(wkp + r*QDQ);
            fma2(a0, pv, wv.x); fma2(a1, pv, wv.y);
        }
        float2 r0 = up2(a0), r1 = up2(a1);
        float4 q4 = *(const float4*)(qv + k);
        float ts = tanhf(r0.x)*q4.x + tanhf(r0.y)*q4.y + tanhf(r1.x)*q4.z + tanhf(r1.y)*q4.w;
        atomicAdd(&wl[s], ts);
    }
    __syncthreads();
    if (tid == 0) {
        float m = -1e30f;
        for (int s = 0; s < TT; s++) { wl[s] *= SCALE; m = fmaxf(m, wl[s]); }
        float sum = 0.f;
        for (int s = 0; s < TT; s++) { float e = __expf(wl[s]-m); wl[s]=e; sum+=e; }
        float inv = 1.f/sum;
        for (int s = 0; s < TT; s++) wl[s] *= inv;
    }
    __syncthreads();
    if (tid < RPR) {
        float a = 0.f;
        #pragma unroll
        for (int s = 0; s < TT; s++) a += wl[s] * val[s*RPR + tid];
        float* outp = (item < BB*CDDN) ? (g_cdd + item*RPR)
                                       : (g_his + (item - BB*CDDN)*RPR);
        outp[tid] = a;
    }
}

// ================= news level: (b,h)-parallel attention =================
// smem: xT[256][52] | qT[256][51] | attn[50][51] | Vh[50][16]
#define NA_XP 52
#define NA_QP 51
#define NA_QT_OFF (256*NA_XP)                 // 13312
#define NA_AT_OFF (NA_QT_OFF + 256*NA_QP)     // 26368
#define NA_V_OFF  (NA_AT_OFF + 50*51 + 2)     // 28920  (16B-aligned)
#define NA_SMEM_FLOATS (NA_V_OFF + 50*16)     // 29720 (118.9 KB)

__global__ __launch_bounds__(256, 1)
void news_attn_kernel(const float* __restrict__ Wq, const float* __restrict__ Wv)
{
    float* xT   = sm;
    float* qT   = sm + NA_QT_OFF;
    float* attn = sm + NA_AT_OFF;
    float* Vh   = sm + NA_V_OFF;

    const int tid = threadIdx.x;
    const int h   = blockIdx.x;
    const int b   = blockIdx.y;
    const float* x = g_his + b*HISN*RPR;     // [50][256]

    for (int p = tid; p < HISN*RPR; p += 256) {
        int f = p & 255, s = p >> 8;
        xT[f*NA_XP + s] = x[p];
    }
    for (int p = tid; p < 512; p += 256)       // zero pad cols 50,51
        xT[(p>>1)*NA_XP + 50 + (p&1)] = 0.f;
    __syncthreads();

    // Vh = x @ Wv_h : 50x4 quad jobs, unroll 4
    if (tid < 200) {
        int s = tid >> 2, v = (tid & 3)*4;
        const float* w = Wv + h*(RPR*VDIM) + v;
        uint64_t a0 = 0, a1 = 0;
        #pragma unroll 4
        for (int f = 0; f < RPR; f++) {
            float xv = xT[f*NA_XP + s];
            uint64_t px = pk2(xv, xv);
            ulonglong2 wv = *(const ulonglong2*)(w + f*VDIM);
            fma2(a0, px, wv.x); fma2(a1, px, wv.y);
        }
        float2 r0 = up2(a0), r1 = up2(a1);
        *(float4*)(Vh + s*16 + v) = make_float4(r0.x, r0.y, r1.x, r1.y);
    }

    // Q_h: thread = column tid, 25 s-pairs; manual unroll-2, Wq loads hoisted
    {
        uint64_t acc[25];
        #pragma unroll
        for (int k = 0; k < 25; k++) acc[k] = 0ull;
        const float* wq = Wq + (size_t)h*(RPR*RPR) + tid;
        #pragma unroll 1
        for (int f = 0; f < RPR; f += 2) {
            float w0 = wq[f*RPR];
            float w1 = wq[(f+1)*RPR];
            {
                uint64_t pw = pk2(w0, w0);
                const ulonglong2* xr = (const ulonglong2*)(xT + f*NA_XP);
                #pragma unroll
                for (int k = 0; k < 12; k++) {
                    ulonglong2 xv = xr[k];
                    fma2(acc[2*k],   xv.x, pw);
                    fma2(acc[2*k+1], xv.y, pw);
                }
                uint64_t xt = *(const uint64_t*)(xT + f*NA_XP + 48);
                fma2(acc[24], xt, pw);
            }
            {
                uint64_t pw = pk2(w1, w1);
                const ulonglong2* xr = (const ulonglong2*)(xT + (f+1)*NA_XP);
                #pragma unroll
                for (int k = 0; k < 12; k++) {
                    ulonglong2 xv = xr[k];
                    fma2(acc[2*k],   xv.x, pw);
                    fma2(acc[2*k+1], xv.y, pw);
                }
                uint64_t xt = *(const uint64_t*)(xT + (f+1)*NA_XP + 48);
                fma2(acc[24], xt, pw);
            }
        }
        float* q0 = qT + tid*NA_QP;
        #pragma unroll
        for (int k = 0; k < 25; k++) {
            float2 a = up2(acc[k]); q0[2*k] = a.x; q0[2*k+1] = a.y;
        }
    }
    __syncthreads();

    // logits: u-quads, 50x13 jobs, unroll 4
    for (int p = tid; p < 650; p += 256) {
        int s = p % 50, uq = p / 50, u = uq*4;
        uint64_t a0 = 0, a1 = 0;
        #pragma unroll 4
        for (int e = 0; e < RPR; e++) {
            float q = qT[e*NA_QP + s];
            uint64_t pq = pk2(q, q);
            ulonglong2 xv = *(const ulonglong2*)(xT + e*NA_XP + u);
            fma2(a0, pq, xv.x); fma2(a1, pq, xv.y);
        }
        float2 r0 = up2(a0), r1 = up2(a1);
        float* ar = attn + s*51;
        ar[u] = r0.x*SCALE;
        if (u+1 < 50) ar[u+1] = r0.y*SCALE;
        if (u+2 < 50) { ar[u+2] = r1.x*SCALE; ar[u+3] = r1.y*SCALE; }
    }
    __syncthreads();

    if (tid < 50) {
        float* row = attn + tid*51;
        float m = row[0];
        for (int u = 1; u < 50; u++) m = fmaxf(m, row[u]);
        float sum = 0.f;
        for (int u = 0; u < 50; u++) { float e = __expf(row[u]-m); row[u]=e; sum+=e; }
        float inv = 1.f/sum;
        for (int u = 0; u < 50; u++) row[u] *= inv;
    }
    __syncthreads();

    for (int p = tid; p < 800; p += 256) {
        int s = p >> 4, v = p & 15;
        const float* ar = attn + s*51;
        float a = 0.f;
        #pragma unroll 10
        for (int u = 0; u < 50; u++) a += ar[u]*Vh[u*16 + v];
        g_nval[(b*HISN + s)*RPR + h*VDIM + v] = a;
    }
}

// ================= news pooling =================
#define NP_SMEM_FLOATS (HISN*RPR + HISN)      // 12850 (51.4 KB)

__global__ __launch_bounds__(256, 2)
void news_pool_kernel(const float* __restrict__ Wk, const float* __restrict__ bk,
                      const float* __restrict__ qv)
{
    float* val = sm;
    float* wl  = sm + HISN*RPR;
    const int tid = threadIdx.x;
    const int b   = blockIdx.x;

    for (int p = tid; p < HISN*RPR; p += 256) val[p] = g_nval[b*HISN*RPR + p];
    if (tid < HISN) wl[tid] = 0.f;
    __syncthreads();

    for (int p = tid; p < HISN*50; p += 256) {
        int s = p/50, kq = p%50, k = kq*4;
        float4 b4 = *(const float4*)(bk + k);
        uint64_t a0 = pk2(b4.x, b4.y), a1 = pk2(b4.z, b4.w);
        const float* vr  = val + s*RPR;
        const float* wkp = Wk + k;
        #pragma unroll 8
        for (int r = 0; r < RPR; r++) {
            uint64_t pv = pk2(vr[r], vr[r]);
            ulonglong2 wv = *(const ulonglong2*)(wkp + r*QDQ);
            fma2(a0, pv, wv.x); fma2(a1, pv, wv.y);
        }
        float2 r0 = up2(a0), r1 = up2(a1);
        float4 q4 = *(const float4*)(qv + k);
        float ts = tanhf(r0.x)*q4.x + tanhf(r0.y)*q4.y + tanhf(r1.x)*q4.z + tanhf(r1.y)*q4.w;
        atomicAdd(&wl[s], ts);
    }
    __syncthreads();
    if (tid == 0) {
        float m = -1e30f;
        for (int s = 0; s < HISN; s++) { wl[s] *= SCALE; m = fmaxf(m, wl[s]); }
        float sum = 0.f;
        for (int s = 0; s < HISN; s++) { float e = __expf(wl[s]-m); wl[s]=e; sum+=e; }
        float inv = 1.f/sum;
        for (int s = 0; s < HISN; s++) wl[s] *= inv;
    }
    __syncthreads();
    if (tid < RPR) {
        float a = 0.f;
        #pragma unroll 10
        for (int s = 0; s < HISN; s++) a += wl[s] * val[s*RPR + tid];
        g_user[b*RPR + tid] = a;
    }
}

// ================= scores + log_softmax =================
__global__ void score_kernel(float* __restrict__ out)
{
    __shared__ float sc[CDDN];
    const int b = blockIdx.x;
    const int w = threadIdx.x >> 5, lane = threadIdx.x & 31;
    if (w < CDDN) {
        const float* c = g_cdd + (b*CDDN + w)*RPR;
        const float* u = g_user + b*RPR;
        float a = 0.f;
        #pragma unroll
        for (int k = lane; k < RPR; k += 32) a += c[k]*u[k];
        #pragma unroll
        for (int off = 16; off; off >>= 1) a += __shfl_down_sync(0xffffffffu, a, off);
        if (lane == 0) sc[w] = a;
    }
    __syncthreads();
    if (threadIdx.x == 0) {
        float m = sc[0];
        for (int c = 1; c < CDDN; c++) m = fmaxf(m, sc[c]);
        float sum = 0.f;
        for (int c = 0; c < CDDN; c++) sum += __expf(sc[c]-m);
        float lse = logf(sum) + m;
        for (int c = 0; c < CDDN; c++) out[b*CDDN + c] = sc[c] - lse;
    }
}

// ================= launch =================
extern "C" void kernel_launch(void* const* d_in, const int* in_sizes, int n_in,
                              void* d_out, int out_size)
{
    (void)in_sizes; (void)n_in; (void)out_size;
    const int*   cand    = (const int*)d_in[0];
    const int*   clicked = (const int*)d_in[1];
    const float* emb     = (const float*)d_in[2];
    const float* Wq_w    = (const float*)d_in[3];
    const float* Wv_w    = (const float*)d_in[4];
    const float* Wk_w    = (const float*)d_in[5];
    const float* bk_w    = (const float*)d_in[6];
    const float* q_w     = (const float*)d_in[7];
    const float* Wq_n    = (const float*)d_in[8];
    const float* Wv_n    = (const float*)d_in[9];
    const float* Wk_n    = (const float*)d_in[10];
    const float* bk_n    = (const float*)d_in[11];
    const float* q_n     = (const float*)d_in[12];
    float* out = (float*)d_out;

    const size_t smw  = W_SMEM_FLOATS  * sizeof(float);
    const size_t smna = NA_SMEM_FLOATS * sizeof(float);
    const size_t smnp = NP_SMEM_FLOATS * sizeof(float);
    cudaFuncSetAttribute(word_kernel,      cudaFuncAttributeMaxDynamicSharedMemorySize, (int)smw);
    cudaFuncSetAttribute(news_attn_kernel, cudaFuncAttributeMaxDynamicSharedMemorySize, (int)smna);
    cudaFuncSetAttribute(news_pool_kernel, cudaFuncAttributeMaxDynamicSharedMemorySize, (int)smnp);

    word_kernel<<<NITEMS, 640, smw>>>(cand, clicked, emb, Wq_w, Wv_w, Wk_w, bk_w, q_w);
    news_attn_kernel<<<dim3(HH, BB), 256, smna>>>(Wq_n, Wv_n);
    news_pool_kernel<<<BB, 256, smnp>>>(Wk_n, bk_n, q_n);
    score_kernel<<<BB, 192>>>(out);
}

// round 6
// speedup vs baseline: 1.5101x; 1.0963x over previous
#include <cuda_runtime.h>
#include <math.h>
#include <stdint.h>

// ---------------- problem constants ----------------
#define BB    256
#define CDDN  5
#define HISN  50
#define TT    20
#define DD    300
#define HH    16
#define VDIM  16
#define RPR   256
#define QDQ   200
#define NITEMS (BB*(CDDN+HISN))
#define SCALE 0.05773502691896258f   // 1/sqrt(300), both levels

// ---------------- device scratch ----------------
__device__ float g_cdd[BB*CDDN*RPR];
__device__ float g_his[BB*HISN*RPR];
__device__ float g_nval[BB*HISN*RPR];
__device__ float g_user[BB*RPR];

// ---------------- packed f32x2 helpers ----------------
__device__ __forceinline__ uint64_t pk2(float a, float b){
    uint64_t r; asm("mov.b64 %0,{%1,%2};" : "=l"(r) : "f"(a), "f"(b)); return r;
}
__device__ __forceinline__ void fma2(uint64_t& d, uint64_t a, uint64_t b){
    asm("fma.rn.f32x2 %0,%1,%2,%0;" : "+l"(d) : "l"(a), "l"(b));
}
__device__ __forceinline__ float2 up2(uint64_t v){
    float2 f; asm("mov.b64 {%0,%1},%2;" : "=f"(f.x), "=f"(f.y) : "l"(v)); return f;
}

extern __shared__ float sm[];

// ================= word-level encoder: one CTA (640 thr) per news item =================
// smem: xT[300][24] | qT[4][300][21] | V[20][256] | val[20][256] | attn[4][20][21] | wl[20]
#define W_XP 24
#define W_QP 21
#define W_QT_OFF  (300*W_XP)                 // 7200
#define W_V_OFF   (W_QT_OFF + 4*300*W_QP)    // 32400
#define W_VAL_OFF (W_V_OFF  + TT*RPR)        // 37520
#define W_ATT_OFF (W_VAL_OFF + TT*RPR)       // 42640
#define W_WL_OFF  (W_ATT_OFF + 4*TT*21)      // 44320
#define W_SMEM_FLOATS (W_WL_OFF + TT)        // 44340  (177.4 KB)

__global__ __launch_bounds__(640, 1)
void word_kernel(const int* __restrict__ cand, const int* __restrict__ clicked,
                 const float* __restrict__ emb,
                 const float* __restrict__ Wq, const float* __restrict__ Wv,
                 const float* __restrict__ Wk, const float* __restrict__ bk,
                 const float* __restrict__ qv)
{
    float* xT   = sm;
    float* qT   = sm + W_QT_OFF;
    float* V    = sm + W_V_OFF;
    float* val  = sm + W_VAL_OFF;
    float* attn = sm + W_ATT_OFF;
    float* wl   = sm + W_WL_OFF;
    __shared__ int tok[TT];

    const int tid  = threadIdx.x;
    const int item = blockIdx.x;

    const int* tp = (item < BB*CDDN) ? (cand + item*TT)
                                     : (clicked + (item - BB*CDDN)*TT);
    if (tid < TT) tok[tid] = tp[tid];
    __syncthreads();

    // gather x transposed
    for (int p = tid; p < TT*DD; p += 640) {
        int s = p / DD, f = p - s*DD;
        xT[f*W_XP + s] = emb[tok[s]*DD + f];
    }
    __syncthreads();

    // ---- V = x @ Wv_all : quad columns, f32x2, MLP-4 on Wv loads ----
    for (int p = tid; p < TT*64; p += 640) {
        int s = p >> 6, cq = p & 63, c = cq*4;
        int h = c >> 4, v = c & 15;
        const float* w = Wv + h*(DD*VDIM) + v;
        uint64_t a0 = 0, a1 = 0;
        #pragma unroll 4
        for (int f = 0; f < DD; f++) {
            float xv = xT[f*W_XP + s];
            uint64_t px = pk2(xv, xv);
            ulonglong2 wv = *(const ulonglong2*)(w + f*VDIM);
            fma2(a0, px, wv.x); fma2(a1, px, wv.y);
        }
        float2 r0 = up2(a0), r1 = up2(a1);
        *(float4*)(V + s*RPR + c) = make_float4(r0.x, r0.y, r1.x, r1.y);
    }
    __syncthreads();

    const int grp = tid / 160;        // 4 head groups of 160 (150 active)
    const int t   = tid % 160;

    for (int g = 0; g < 4; g++) {
        // ---- Q for 4 heads: thread owns 2 columns; software-pipelined
        //      Wq prefetch (load f+2/f+3 before consuming f/f+1) ----
        if (t < 150) {
            const int h = g*4 + grp;
            const float* wq = Wq + (size_t)h*(DD*DD) + 2*t;
            uint64_t acc[20];
            #pragma unroll
            for (int k = 0; k < 20; k++) acc[k] = 0ull;
            float2 wA = *(const float2*)(wq);
            float2 wB = *(const float2*)(wq + DD);
            #pragma unroll 1
            for (int f = 0; f < DD; f += 2) {
                // prefetch next pair (clamped; last-iter values unused)
                int fn = (f + 2 < DD) ? (f + 2) : 0;
                float2 nA = *(const float2*)(wq + fn*DD);
                float2 nB = *(const float2*)(wq + (fn+1)*DD);
                {
                    uint64_t p0 = pk2(wA.x, wA.x), p1 = pk2(wA.y, wA.y);
                    const ulonglong2* xr = (const ulonglong2*)(xT + f*W_XP);
                    ulonglong2 x0 = xr[0], x1 = xr[1], x2 = xr[2], x3 = xr[3], x4 = xr[4];
                    fma2(acc[0], x0.x, p0);  fma2(acc[10], x0.x, p1);
                    fma2(acc[1], x0.y, p0);  fma2(acc[11], x0.y, p1);
                    fma2(acc[2], x1.x, p0);  fma2(acc[12], x1.x, p1);
                    fma2(acc[3], x1.y, p0);  fma2(acc[13], x1.y, p1);
                    fma2(acc[4], x2.x, p0);  fma2(acc[14], x2.x, p1);
                    fma2(acc[5], x2.y, p0);  fma2(acc[15], x2.y, p1);
                    fma2(acc[6], x3.x, p0);  fma2(acc[16], x3.x, p1);
                    fma2(acc[7], x3.y, p0);  fma2(acc[17], x3.y, p1);
                    fma2(acc[8], x4.x, p0);  fma2(acc[18], x4.x, p1);
                    fma2(acc[9], x4.y, p0);  fma2(acc[19], x4.y, p1);
                }
                {
                    uint64_t p0 = pk2(wB.x, wB.x), p1 = pk2(wB.y, wB.y);
                    const ulonglong2* xr = (const ulonglong2*)(xT + (f+1)*W_XP);
                    ulonglong2 x0 = xr[0], x1 = xr[1], x2 = xr[2], x3 = xr[3], x4 = xr[4];
                    fma2(acc[0], x0.x, p0);  fma2(acc[10], x0.x, p1);
                    fma2(acc[1], x0.y, p0);  fma2(acc[11], x0.y, p1);
                    fma2(acc[2], x1.x, p0);  fma2(acc[12], x1.x, p1);
                    fma2(acc[3], x1.y, p0);  fma2(acc[13], x1.y, p1);
                    fma2(acc[4], x2.x, p0);  fma2(acc[14], x2.x, p1);
                    fma2(acc[5], x2.y, p0);  fma2(acc[15], x2.y, p1);
                    fma2(acc[6], x3.x, p0);  fma2(acc[16], x3.x, p1);
                    fma2(acc[7], x3.y, p0);  fma2(acc[17], x3.y, p1);
                    fma2(acc[8], x4.x, p0);  fma2(acc[18], x4.x, p1);
                    fma2(acc[9], x4.y, p0);  fma2(acc[19], x4.y, p1);
                }
                wA = nA; wB = nB;
            }
            float* q0 = qT + grp*(300*W_QP) + (2*t)*W_QP;
            float* q1 = q0 + W_QP;
            #pragma unroll
            for (int k = 0; k < 10; k++) {
                float2 a = up2(acc[k]);    q0[2*k] = a.x; q0[2*k+1] = a.y;
                float2 b = up2(acc[10+k]); q1[2*k] = b.x; q1[2*k+1] = b.y;
            }
        }
        __syncthreads();

        // ---- logits: u-quad per thread (4 heads x 100), unroll 4 ----
        if (tid < 400) {
            int hl = tid/100, r = tid%100, s = r%20, uq = r/20;
            const float* qh = qT + hl*(300*W_QP);
            uint64_t a0 = 0, a1 = 0;
            #pragma unroll 4
            for (int e = 0; e < DD; e++) {
                float q = qh[e*W_QP + s];
                uint64_t pq = pk2(q, q);
                ulonglong2 xv = *(const ulonglong2*)(xT + e*W_XP + uq*4);
                fma2(a0, pq, xv.x); fma2(a1, pq, xv.y);
            }
            float2 r0 = up2(a0), r1 = up2(a1);
            float* ar = attn + (hl*TT + s)*21 + uq*4;
            ar[0]=r0.x*SCALE; ar[1]=r0.y*SCALE; ar[2]=r1.x*SCALE; ar[3]=r1.y*SCALE;
        }
        __syncthreads();

        // ---- softmax rows (4 heads x 20) ----
        if (tid < 80) {
            float* row = attn + tid*21;
            float m = row[0];
            #pragma unroll
            for (int u = 1; u < TT; u++) m = fmaxf(m, row[u]);
            float sum = 0.f;
            #pragma unroll
            for (int u = 0; u < TT; u++) { float e = __expf(row[u]-m); row[u]=e; sum+=e; }
            float inv = 1.f/sum;
            #pragma unroll
            for (int u = 0; u < TT; u++) row[u] *= inv;
        }
        __syncthreads();

        // ---- val = attn @ V (4 heads) ----
        for (int p = tid; p < 4*TT*VDIM; p += 640) {
            int hl = p/320, rm = p%320, s = rm>>4, v = rm&15;
            int h = g*4 + hl;
            const float* ar = attn + (hl*TT + s)*21;
            const float* vc = V + h*VDIM + v;
            float a = 0.f;
            #pragma unroll
            for (int u = 0; u < TT; u++) a += ar[u]*vc[u*RPR];
            val[s*RPR + h*VDIM + v] = a;
        }
        __syncthreads();
    }

    // ---- additive pooling: k-quads, f32x2, MLP-8 on Wk loads ----
    if (tid < TT) wl[tid] = 0.f;
    __syncthreads();
    for (int p = tid; p < TT*50; p += 640) {
        int s = p/50, kq = p%50, k = kq*4;
        float4 b4 = *(const float4*)(bk + k);
        uint64_t a0 = pk2(b4.x, b4.y), a1 = pk2(b4.z, b4.w);
        const float* vr  = val + s*RPR;
        const float* wkp = Wk + k;
        #pragma unroll 8
        for (int r = 0; r < RPR; r++) {
            uint64_t pv = pk2(vr[r], vr[r]);
            ulonglong2 wv = *(const ulonglong2*)(wkp + r*QDQ);
            fma2(a0, pv, wv.x); fma2(a1, pv, wv.y);
        }
        float2 r0 = up2(a0), r1 = up2(a1);
        float4 q4 = *(const float4*)(qv + k);
        float ts = tanhf(r0.x)*q4.x + tanhf(r0.y)*q4.y + tanhf(r1.x)*q4.z + tanhf(r1.y)*q4.w;
        atomicAdd(&wl[s], ts);
    }
    __syncthreads();
    if (tid == 0) {
        float m = -1e30f;
        for (int s = 0; s < TT; s++) { wl[s] *= SCALE; m = fmaxf(m, wl[s]); }
        float sum = 0.f;
        for (int s = 0; s < TT; s++) { float e = __expf(wl[s]-m); wl[s]=e; sum+=e; }
        float inv = 1.f/sum;
        for (int s = 0; s < TT; s++) wl[s] *= inv;
    }
    __syncthreads();
    if (tid < RPR) {
        float a = 0.f;
        #pragma unroll
        for (int s = 0; s < TT; s++) a += wl[s] * val[s*RPR + tid];
        float* outp = (item < BB*CDDN) ? (g_cdd + item*RPR)
                                       : (g_his + (item - BB*CDDN)*RPR);
        outp[tid] = a;
    }
}

// ================= news level: (b,h)-parallel attention =================
// smem: xT[256][52] | qT[256][51] | attn[50][51] | Vh[50][16]
#define NA_XP 52
#define NA_QP 51
#define NA_QT_OFF (256*NA_XP)                 // 13312
#define NA_AT_OFF (NA_QT_OFF + 256*NA_QP)     // 26368
#define NA_V_OFF  (NA_AT_OFF + 50*51 + 2)     // 28920  (16B-aligned)
#define NA_SMEM_FLOATS (NA_V_OFF + 50*16)     // 29720 (118.9 KB)

__global__ __launch_bounds__(256, 1)
void news_attn_kernel(const float* __restrict__ Wq, const float* __restrict__ Wv)
{
    float* xT   = sm;
    float* qT   = sm + NA_QT_OFF;
    float* attn = sm + NA_AT_OFF;
    float* Vh   = sm + NA_V_OFF;

    const int tid = threadIdx.x;
    const int h   = blockIdx.x;
    const int b   = blockIdx.y;
    const float* x = g_his + b*HISN*RPR;     // [50][256]

    for (int p = tid; p < HISN*RPR; p += 256) {
        int f = p & 255, s = p >> 8;
        xT[f*NA_XP + s] = x[p];
    }
    for (int p = tid; p < 512; p += 256)       // zero pad cols 50,51
        xT[(p>>1)*NA_XP + 50 + (p&1)] = 0.f;
    __syncthreads();

    // Vh = x @ Wv_h : 50x4 quad jobs, unroll 4
    if (tid < 200) {
        int s = tid >> 2, v = (tid & 3)*4;
        const float* w = Wv + h*(RPR*VDIM) + v;
        uint64_t a0 = 0, a1 = 0;
        #pragma unroll 4
        for (int f = 0; f < RPR; f++) {
            float xv = xT[f*NA_XP + s];
            uint64_t px = pk2(xv, xv);
            ulonglong2 wv = *(const ulonglong2*)(w + f*VDIM);
            fma2(a0, px, wv.x); fma2(a1, px, wv.y);
        }
        float2 r0 = up2(a0), r1 = up2(a1);
        *(float4*)(Vh + s*16 + v) = make_float4(r0.x, r0.y, r1.x, r1.y);
    }

    // Q_h: thread = column tid, 25 s-pairs; software-pipelined Wq prefetch
    {
        uint64_t acc[25];
        #pragma unroll
        for (int k = 0; k < 25; k++) acc[k] = 0ull;
        const float* wq = Wq + (size_t)h*(RPR*RPR) + tid;
        float w0 = wq[0];
        float w1 = wq[RPR];
        #pragma unroll 1
        for (int f = 0; f < RPR; f += 2) {
            int fn = (f + 2 < RPR) ? (f + 2) : 0;
            float n0 = wq[fn*RPR];
            float n1 = wq[(fn+1)*RPR];
            {
                uint64_t pw = pk2(w0, w0);
                const ulonglong2* xr = (const ulonglong2*)(xT + f*NA_XP);
                #pragma unroll
                for (int k = 0; k < 12; k++) {
                    ulonglong2 xv = xr[k];
                    fma2(acc[2*k],   xv.x, pw);
                    fma2(acc[2*k+1], xv.y, pw);
                }
                uint64_t xt = *(const uint64_t*)(xT + f*NA_XP + 48);
                fma2(acc[24], xt, pw);
            }
            {
                uint64_t pw = pk2(w1, w1);
                const ulonglong2* xr = (const ulonglong2*)(xT + (f+1)*NA_XP);
                #pragma unroll
                for (int k = 0; k < 12; k++) {
                    ulonglong2 xv = xr[k];
                    fma2(acc[2*k],   xv.x, pw);
                    fma2(acc[2*k+1], xv.y, pw);
                }
                uint64_t xt = *(const uint64_t*)(xT + (f+1)*NA_XP + 48);
                fma2(acc[24], xt, pw);
            }
            w0 = n0; w1 = n1;
        }
        float* q0 = qT + tid*NA_QP;
        #pragma unroll
        for (int k = 0; k < 25; k++) {
            float2 a = up2(acc[k]); q0[2*k] = a.x; q0[2*k+1] = a.y;
        }
    }
    __syncthreads();

    // logits: u-quads, 50x13 jobs, unroll 4
    for (int p = tid; p < 650; p += 256) {
        int s = p % 50, uq = p / 50, u = uq*4;
        uint64_t a0 = 0, a1 = 0;
        #pragma unroll 4
        for (int e = 0; e < RPR; e++) {
            float q = qT[e*NA_QP + s];
            uint64_t pq = pk2(q, q);
            ulonglong2 xv = *(const ulonglong2*)(xT + e*NA_XP + u);
            fma2(a0, pq, xv.x); fma2(a1, pq, xv.y);
        }
        float2 r0 = up2(a0), r1 = up2(a1);
        float* ar = attn + s*51;
        ar[u] = r0.x*SCALE;
        if (u+1 < 50) ar[u+1] = r0.y*SCALE;
        if (u+2 < 50) { ar[u+2] = r1.x*SCALE; ar[u+3] = r1.y*SCALE; }
    }
    __syncthreads();

    if (tid < 50) {
        float* row = attn + tid*51;
        float m = row[0];
        for (int u = 1; u < 50; u++) m = fmaxf(m, row[u]);
        float sum = 0.f;
        for (int u = 0; u < 50; u++) { float e = __expf(row[u]-m); row[u]=e; sum+=e; }
        float inv = 1.f/sum;
        for (int u = 0; u < 50; u++) row[u] *= inv;
    }
    __syncthreads();

    for (int p = tid; p < 800; p += 256) {
        int s = p >> 4, v = p & 15;
        const float* ar = attn + s*51;
        float a = 0.f;
        #pragma unroll 10
        for (int u = 0; u < 50; u++) a += ar[u]*Vh[u*16 + v];
        g_nval[(b*HISN + s)*RPR + h*VDIM + v] = a;
    }
}

// ================= news pooling =================
#define NP_SMEM_FLOATS (HISN*RPR + HISN)      // 12850 (51.4 KB)

__global__ __launch_bounds__(256, 2)
void news_pool_kernel(const float* __restrict__ Wk, const float* __restrict__ bk,
                      const float* __restrict__ qv)
{
    float* val = sm;
    float* wl  = sm + HISN*RPR;
    const int tid = threadIdx.x;
    const int b   = blockIdx.x;

    for (int p = tid; p < HISN*RPR; p += 256) val[p] = g_nval[b*HISN*RPR + p];
    if (tid < HISN) wl[tid] = 0.f;
    __syncthreads();

    for (int p = tid; p < HISN*50; p += 256) {
        int s = p/50, kq = p%50, k = kq*4;
        float4 b4 = *(const float4*)(bk + k);
        uint64_t a0 = pk2(b4.x, b4.y), a1 = pk2(b4.z, b4.w);
        const float* vr  = val + s*RPR;
        const float* wkp = Wk + k;
        #pragma unroll 8
        for (int r = 0; r < RPR; r++) {
            uint64_t pv = pk2(vr[r], vr[r]);
            ulonglong2 wv = *(const ulonglong2*)(wkp + r*QDQ);
            fma2(a0, pv, wv.x); fma2(a1, pv, wv.y);
        }
        float2 r0 = up2(a0), r1 = up2(a1);
        float4 q4 = *(const float4*)(qv + k);
        float ts = tanhf(r0.x)*q4.x + tanhf(r0.y)*q4.y + tanhf(r1.x)*q4.z + tanhf(r1.y)*q4.w;
        atomicAdd(&wl[s], ts);
    }
    __syncthreads();
    if (tid == 0) {
        float m = -1e30f;
        for (int s = 0; s < HISN; s++) { wl[s] *= SCALE; m = fmaxf(m, wl[s]); }
        float sum = 0.f;
        for (int s = 0; s < HISN; s++) { float e = __expf(wl[s]-m); wl[s]=e; sum+=e; }
        float inv = 1.f/sum;
        for (int s = 0; s < HISN; s++) wl[s] *= inv;
    }
    __syncthreads();
    if (tid < RPR) {
        float a = 0.f;
        #pragma unroll 10
        for (int s = 0; s < HISN; s++) a += wl[s] * val[s*RPR + tid];
        g_user[b*RPR + tid] = a;
    }
}

// ================= scores + log_softmax =================
__global__ void score_kernel(float* __restrict__ out)
{
    __shared__ float sc[CDDN];
    const int b = blockIdx.x;
    const int w = threadIdx.x >> 5, lane = threadIdx.x & 31;
    if (w < CDDN) {
        const float* c = g_cdd + (b*CDDN + w)*RPR;
        const float* u = g_user + b*RPR;
        float a = 0.f;
        #pragma unroll
        for (int k = lane; k < RPR; k += 32) a += c[k]*u[k];
        #pragma unroll
        for (int off = 16; off; off >>= 1) a += __shfl_down_sync(0xffffffffu, a, off);
        if (lane == 0) sc[w] = a;
    }
    __syncthreads();
    if (threadIdx.x == 0) {
        float m = sc[0];
        for (int c = 1; c < CDDN; c++) m = fmaxf(m, sc[c]);
        float sum = 0.f;
        for (int c = 0; c < CDDN; c++) sum += __expf(sc[c]-m);
        float lse = logf(sum) + m;
        for (int c = 0; c < CDDN; c++) out[b*CDDN + c] = sc[c] - lse;
    }
}

// ================= launch =================
extern "C" void kernel_launch(void* const* d_in, const int* in_sizes, int n_in,
                              void* d_out, int out_size)
{
    (void)in_sizes; (void)n_in; (void)out_size;
    const int*   cand    = (const int*)d_in[0];
    const int*   clicked = (const int*)d_in[1];
    const float* emb     = (const float*)d_in[2];
    const float* Wq_w    = (const float*)d_in[3];
    const float* Wv_w    = (const float*)d_in[4];
    const float* Wk_w    = (const float*)d_in[5];
    const float* bk_w    = (const float*)d_in[6];
    const float* q_w     = (const float*)d_in[7];
    const float* Wq_n    = (const float*)d_in[8];
    const float* Wv_n    = (const float*)d_in[9];
    const float* Wk_n    = (const float*)d_in[10];
    const float* bk_n    = (const float*)d_in[11];
    const float* q_n     = (const float*)d_in[12];
    float* out = (float*)d_out;

    const size_t smw  = W_SMEM_FLOATS  * sizeof(float);
    const size_t smna = NA_SMEM_FLOATS * sizeof(float);
    const size_t smnp = NP_SMEM_FLOATS * sizeof(float);
    cudaFuncSetAttribute(word_kernel,      cudaFuncAttributeMaxDynamicSharedMemorySize, (int)smw);
    cudaFuncSetAttribute(news_attn_kernel, cudaFuncAttributeMaxDynamicSharedMemorySize, (int)smna);
    cudaFuncSetAttribute(news_pool_kernel, cudaFuncAttributeMaxDynamicSharedMemorySize, (int)smnp);

    word_kernel<<<NITEMS, 640, smw>>>(cand, clicked, emb, Wq_w, Wv_w, Wk_w, bk_w, q_w);
    news_attn_kernel<<<dim3(HH, BB), 256, smna>>>(Wq_n, Wv_n);
    news_pool_kernel<<<BB, 256, smnp>>>(Wk_n, bk_n, q_n);
    score_kernel<<<BB, 192>>>(out);
}